// round 12
// baseline (speedup 1.0000x reference)
#include <cuda_runtime.h>
#include <math_constants.h>

#define NPTS   8192
#define WID    8193
#define NCH    65536          // 8192 rows * 8 chunks (shifted windows)
#define NT     64
#define KCORR  2048
#define MARGIN 1e-4f
#define LOGNEG (-1e30f)
#define NB     128            // sparse-kernel blocks (co-resident on 148 SMs)
#define NTHR   512
#define CAPC   (1 << 17)      // candidate buffer
#define SKEYS  12288          // smem key cache

// ------------- device scratch (zero-init at load; kernels restore what they dirty)
__device__ float    d_logs4[4][NPTS];    // pass1: copy s = logf(src[j+s]) / pad
__device__ float    d_logsp[NPTS + 8];   // sparse: logf(src[j]), padded LOGNEG
__device__ float    d_logr[NPTS];
__device__ float    d_chunkmax[NCH];
__device__ unsigned d_chist[NT];
__device__ unsigned d_ehist[NT];
__device__ unsigned d_tkA, d_tkB, d_tkC, d_tkD;
__device__ unsigned d_flagA, d_flagB;
__device__ unsigned d_nl;
__device__ float    d_thres;
__device__ unsigned d_nsel;              // exact selected count (from hist)
__device__ unsigned d_nc;                // candidate counter
__device__ unsigned d_ckey[CAPC];
__device__ float    d_cv[CAPC];

__device__ __forceinline__ float table_at(int n) {
    float tv = 0.5f;                     // exact fp32 replication of t -= 0.01f
    for (int j = 0; j < n; ++j) tv -= 0.01f;
    return tv;
}

// ==================== K0: log tables ====================
__global__ void k_init(const float* __restrict__ ref, const float* __restrict__ src) {
    const int i = blockIdx.x * 256 + threadIdx.x;   // 0..8191
    if (i < NPTS) {
        d_logr[i]  = logf(ref[i]);
        d_logsp[i] = logf(src[i]);
#pragma unroll
        for (int s = 0; s < 4; ++s)
            d_logs4[s][i] = (i + s < NPTS) ? logf(src[i + s]) : LOGNEG;
    }
    if (i < 8) d_logsp[NPTS + i] = LOGNEG;
}

// ==================== K1: single full 268MB pass, float4 (unchanged) =========
__global__ void __launch_bounds__(256) k_pass1(const float* __restrict__ ms) {
    __shared__ float    s_logt[NT];
    __shared__ unsigned s_h[NT];
    __shared__ unsigned s_last;
    const int c = blockIdx.x & 7, rg = blockIdx.x >> 3, t = threadIdx.x;
    if (t < NT) {
        const float tv = table_at(t);
        s_logt[t] = (tv > 0.0f) ? logf(tv) : LOGNEG;
        s_h[t] = 0u;
    }
    __syncthreads();

    const int lane = t & 31, w = t >> 5;
    for (int rr = 0; rr < 8; ++rr) {
        const int row = rg * 64 + w * 8 + rr;
        const int s = (4 - (row & 3)) & 3;
        const float4* __restrict__ p4 =
            (const float4*)(ms + (size_t)row * WID + c * 1024 + s);
        const float4* __restrict__ q4 = (const float4*)(&d_logs4[s][c * 1024]);
        float m = -CUDART_INF_F;
#pragma unroll
        for (int k = 0; k < 8; ++k) {
            const float4 a = p4[k * 32 + lane];
            const float4 b = q4[k * 32 + lane];
            m = fmaxf(m, fmaxf(fmaxf(a.x + b.x, a.y + b.y),
                               fmaxf(a.z + b.z, a.w + b.w)));
        }
        if (c == 0 && lane < s)
            m = fmaxf(m, ms[(size_t)row * WID + lane] + d_logs4[0][lane]);
        m += d_logr[row];
#pragma unroll
        for (int o = 16; o; o >>= 1) m = fmaxf(m, __shfl_xor_sync(0xffffffffu, m, o));
        if (lane == 0) {
            d_chunkmax[row * 8 + c] = m;
            int lo = 0, hi = NT;
            while (lo < hi) { int mid = (lo + hi) >> 1; if (s_logt[mid] + MARGIN < m) hi = mid; else lo = mid + 1; }
            if (lo < NT) atomicAdd(&s_h[lo], 1u);
        }
    }
    __syncthreads();
    if (t < NT && s_h[t]) atomicAdd(&d_chist[t], s_h[t]);
    __threadfence();
    __syncthreads();
    if (t == 0) s_last = (atomicAdd(&d_tkA, 1u) == gridDim.x - 1) ? 1u : 0u;
    __syncthreads();
    if (s_last) {
        if (t < NT) s_h[t] = atomicAdd(&d_chist[t], 0u);
        __syncthreads();
        if (t == 0) {
            unsigned cum = 0; int nl = NT - 1;
            for (int n = 0; n < NT; ++n) { cum += s_h[n]; if (cum >= KCORR) { nl = n; break; } }
            d_nl  = (unsigned)nl;
            d_tkA = 0u;
        }
        if (t < NT) d_chist[t] = 0u;
    }
}

// ==================== K2: one sparse walk + rank-ordered emission ============
__global__ void __launch_bounds__(NTHR) k_sparse(const float* __restrict__ ms,
                                                 const float* __restrict__ ref,
                                                 const float* __restrict__ src,
                                                 float* __restrict__ out, int seg) {
    __shared__ float    tt[NT];
    __shared__ unsigned h[NT];
    __shared__ unsigned s_last;
    __shared__ unsigned s_keys[SKEYS];
    const int t = threadIdx.x, lane = t & 31, w = t >> 5;
    if (t < NT) { tt[t] = table_at(t); h[t] = 0u; }
    __syncthreads();

    const int nl = (int)d_nl;
    const float tnl  = tt[nl];
    const float cutL = ((tnl > 0.0f) ? logf(tnl) : LOGNEG) - MARGIN;
    const int chunk0 = blockIdx.x * NTHR + w * 32;

    // ---------------- phase A: ONE walk — extract candidates + exact hist -----
    unsigned act = __ballot_sync(0xffffffffu, d_chunkmax[chunk0 + lane] > cutL);
    while (act) {
        const int i = __ffs(act) - 1; act &= act - 1;
        const int chunk = chunk0 + i;
        const int row = chunk >> 3, c = chunk & 7, s = (4 - (row & 3)) & 3;
        const float lr = d_logr[row];
        const float rr = ref[row];
        const float* __restrict__ p = ms + (size_t)row * WID;

        // head columns [0,s) fold into chunk 0
        if (c == 0) {
            bool pred = false; float v = 0.0f;
            if (lane < s) {
                const float L = (p[lane] + d_logsp[lane]) + lr;
                if (L > cutL) { v = expf(p[lane]) * (rr * src[lane]); pred = true; }
            }
            const unsigned mk = __ballot_sync(0xffffffffu, pred);
            if (mk) {
                unsigned base;
                const int leader = __ffs(mk) - 1;
                if (lane == leader) base = atomicAdd(&d_nc, (unsigned)__popc(mk));
                base = __shfl_sync(0xffffffffu, base, leader);
                if (pred) {
                    const unsigned pos = base + __popc(mk & ((1u << lane) - 1u));
                    if (pos < CAPC) {
                        d_ckey[pos] = ((unsigned)row << 13) | (unsigned)lane;
                        d_cv[pos]   = v;
                    }
                    int lo = 0, hi = NT - 1;          // first n with tt[n] < v
                    while (lo < hi) { int mid = (lo + hi) >> 1; if (tt[mid] < v) hi = mid; else lo = mid + 1; }
                    atomicAdd(&h[lo], 1u);
                }
            }
        }
        const int col0 = c * 1024 + s + lane;
        float Ls[32];
#pragma unroll
        for (int it = 0; it < 32; ++it)               // pads give L = -1e30
            Ls[it] = (p[col0 + it * 32] + d_logsp[col0 + it * 32]) + lr;
#pragma unroll
        for (int it = 0; it < 32; ++it) {
            const bool pred = Ls[it] > cutL;
            const unsigned mk = __ballot_sync(0xffffffffu, pred);
            if (!mk) continue;
            unsigned base;
            const int leader = __ffs(mk) - 1;
            if (lane == leader) base = atomicAdd(&d_nc, (unsigned)__popc(mk));
            base = __shfl_sync(0xffffffffu, base, leader);
            if (pred) {
                const int col = col0 + it * 32;
                const float v = expf(p[col]) * (rr * src[col]);  // exact ref expr
                const unsigned pos = base + __popc(mk & ((1u << lane) - 1u));
                if (pos < CAPC) {
                    d_ckey[pos] = ((unsigned)row << 13) | (unsigned)col;
                    d_cv[pos]   = v;
                }
                int lo = 0, hi = NT - 1;
                while (lo < hi) { int mid = (lo + hi) >> 1; if (tt[mid] < v) hi = mid; else lo = mid + 1; }
                atomicAdd(&h[lo], 1u);
            }
        }
    }
    __syncthreads();
    if (t < NT && h[t]) atomicAdd(&d_ehist[t], h[t]);
    __threadfence();
    __syncthreads();
    if (t == 0) s_last = (atomicAdd(&d_tkB, 1u) == gridDim.x - 1) ? 1u : 0u;
    __syncthreads();
    if (s_last) {
        if (t < NT) h[t] = atomicAdd(&d_ehist[t], 0u);
        __syncthreads();
        if (t == 0) {
            unsigned cum = 0; int pick = NT - 1;
            for (int n = 0; n < NT; ++n) { cum += h[n]; if (cum >= KCORR) { pick = n; break; } }
            d_thres = tt[pick];
            d_nsel  = cum;                 // exact count(thres)
            d_tkB   = 0u;
        }
        if (t < NT) d_ehist[t] = 0u;
        __threadfence();
        __syncthreads();
        if (t == 0) atomicExch(&d_flagA, 1u);
    }
    if (t == 0) { while (atomicAdd(&d_flagA, 0u) == 0u) __nanosleep(100); }
    __syncthreads();
    __threadfence();

    const float thres = d_thres;
    const unsigned C  = min(d_nc, (unsigned)CAPC);
    const unsigned gtid = blockIdx.x * NTHR + t, gsz = gridDim.x * NTHR;

    // ---------------- phase B1: mark selected (bit 31 of key) ----------------
    for (unsigned i = gtid; i < C; i += gsz)
        if (d_cv[i] > thres) d_ckey[i] |= 0x80000000u;
    __threadfence();
    __syncthreads();
    if (t == 0) {
        if (atomicAdd(&d_tkC, 1u) == gridDim.x - 1) {
            d_tkC = 0u;
            __threadfence();
            atomicExch(&d_flagB, 1u);
        }
        while (atomicAdd(&d_flagB, 0u) == 0u) __nanosleep(100);
    }
    __syncthreads();
    __threadfence();

    // ---------------- phase B2: rank-based ordered emission + padding --------
    const bool use_s = (C <= (unsigned)SKEYS);
    if (use_s) for (unsigned j = t; j < C; j += NTHR) s_keys[j] = d_ckey[j];
    __syncthreads();

    const unsigned lim = (unsigned)min(seg, NPTS);
    for (unsigned i = gtid; i < C; i += gsz) {
        const unsigned ki = d_ckey[i];
        if (ki & 0x80000000u) {
            unsigned rank = 0;
            if (use_s) {
                for (unsigned j = 0; j < C; ++j) {
                    const unsigned kj = s_keys[j];
                    rank += (kj > 0x7FFFFFFFu && kj < ki) ? 1u : 0u;
                }
            } else {
                for (unsigned j = 0; j < C; ++j) {
                    const unsigned kj = d_ckey[j];
                    rank += (kj > 0x7FFFFFFFu && kj < ki) ? 1u : 0u;
                }
            }
            if (rank < lim) {
                const unsigned klow = ki & 0x7FFFFFFFu;
                out[rank]           = (float)(klow >> 13);
                out[seg + rank]     = (float)(klow & 8191u);
                out[2 * seg + rank] = d_cv[i];
            }
        }
    }
    // padding: valid = idx < count
    {
        const unsigned start = min(d_nsel, lim);
        for (unsigned i2 = start + gtid; i2 < (unsigned)seg; i2 += gsz) {
            out[i2] = -1.0f; out[seg + i2] = -1.0f; out[2 * seg + i2] = 0.0f;
        }
    }
    // final reset (all blocks are past both polls and all reads of d_nc)
    __syncthreads();
    if (t == 0) {
        if (atomicAdd(&d_tkD, 1u) == gridDim.x - 1) {
            d_flagA = 0u; d_flagB = 0u; d_nc = 0u; d_tkD = 0u;
            __threadfence();
        }
    }
}

// ---------------- launch ----------------
extern "C" void kernel_launch(void* const* d_in, const int* in_sizes, int n_in,
                              void* d_out, int out_size) {
    const float* ms  = (const float*)d_in[0];
    const float* ref = (const float*)d_in[1];
    const float* src = (const float*)d_in[2];
    float* out = (float*)d_out;
    const int seg = out_size / 3;

    k_init  <<<32, 256>>>(ref, src);
    k_pass1 <<<1024, 256>>>(ms);
    k_sparse<<<NB, NTHR>>>(ms, ref, src, out, seg);
}